// round 15
// baseline (speedup 1.0000x reference)
#include <cuda_runtime.h>
#include <cuda_bf16.h>
#include <cstdint>
#include <math.h>

#define BB    4
#define NN    8192
#define IND   1024
#define HID   512
#define HEADS 8
#define DH    64
#define KTOP  16
#define NCLSD 2
#define HG    91
#define NP    (HG*HG)    /* 8281 */
#define NT    (NP+1)     /* 8282 */
#define MROWS (BB*NN)    /* 32768 */

// ---------------- scratch (device globals; no allocation allowed) ------------
__device__ float g_x[(size_t)MROWS*HID];           // post-feature GEMM (67 MB)
__device__ unsigned short g_Ah[(size_t)MROWS*IND]; // inputs hi bf16 (64 MB)
__device__ unsigned short g_Al[(size_t)MROWS*IND]; // inputs lo bf16 (64 MB)
__device__ unsigned short g_Wth[(size_t)HID*IND];  // W^T hi bf16
__device__ unsigned short g_Wtl[(size_t)HID*IND];  // W^T lo bf16
__device__ __align__(16) float g_v[IND + 4];       // folded score vector + const
__device__ float g_scores[MROWS];
__device__ float g_Q[BB*HID];
__device__ float g_y[(size_t)BB*NP*HID];           // post-conv tokens (68 MB)
__device__ float g_q[BB*HID];
__device__ float g_qWk[BB*HEADS*HID];
__device__ float g_qbk[BB*HEADS];
__device__ float g_sume[BB*HEADS];
__device__ float g_ctx[BB*HEADS*HID];
__device__ float g_sO[BB*HID];

// =================== PTX helpers (arch-portable: ldmatrix/mma/cp.async) ======
__device__ __forceinline__ uint32_t smem_u32(const void* p) {
    uint32_t a;
    asm("{ .reg .u64 t; cvta.to.shared.u64 t, %1; cvt.u32.u64 %0, t; }"
        : "=r"(a) : "l"(p));
    return a;
}
__device__ __forceinline__ void ldsm_x4(uint32_t addr, uint32_t* r) {
    asm volatile("ldmatrix.sync.aligned.m8n8.x4.shared.b16 {%0,%1,%2,%3}, [%4];"
                 : "=r"(r[0]), "=r"(r[1]), "=r"(r[2]), "=r"(r[3]) : "r"(addr));
}
__device__ __forceinline__ void mma16816(float* c, const uint32_t* a,
                                         const uint32_t* b) {
    asm volatile(
        "mma.sync.aligned.m16n8k16.row.col.f32.bf16.bf16.f32 "
        "{%0,%1,%2,%3}, {%4,%5,%6,%7}, {%8,%9}, {%0,%1,%2,%3};"
        : "+f"(c[0]), "+f"(c[1]), "+f"(c[2]), "+f"(c[3])
        : "r"(a[0]), "r"(a[1]), "r"(a[2]), "r"(a[3]), "r"(b[0]), "r"(b[1]));
}
__device__ __forceinline__ void cp_async16(uint32_t saddr, const void* gptr) {
    asm volatile("cp.async.cg.shared.global [%0], [%1], 16;"
                 :: "r"(saddr), "l"(gptr));
}
#define CP_COMMIT() asm volatile("cp.async.commit_group;" ::: "memory")
#define CP_WAIT2()  asm volatile("cp.async.wait_group 2;" ::: "memory")

// ---------------- 0) merged preprocessing: W^T bf16 hi/lo  +  fold vector ----
__global__ void __launch_bounds__(256) prep_weights(const float* __restrict__ W,
                                                    const float* __restrict__ w_enc,
                                                    const float* __restrict__ b_feat,
                                                    const float* __restrict__ b_enc)
{
    int bx = blockIdx.x;
    if (bx < 2048) {                       // convert_W part
        int idx = bx * 256 + threadIdx.x;
        int n = idx >> 10, k = idx & 1023;
        float v = W[(size_t)k * HID + n];
        __nv_bfloat16 h = __float2bfloat16(v);
        __nv_bfloat16 l = __float2bfloat16(v - __bfloat162float(h));
        g_Wth[idx] = *(unsigned short*)&h;
        g_Wtl[idx] = *(unsigned short*)&l;
        return;
    }
    // fold part: blocks 2048..2176
    int warp = threadIdx.x >> 5, lane = threadIdx.x & 31;
    int k = (bx - 2048) * 8 + warp;
    if (k < IND) {
        const float* Wr = W + (size_t)k * HID;
        float sum = 0.f;
#pragma unroll
        for (int i = 0; i < 4; i++) {
            float4 a = *(const float4*)(Wr + lane * 4 + i * 128);
            float4 b = *(const float4*)(w_enc + lane * 4 + i * 128);
            sum += a.x * b.x + a.y * b.y + a.z * b.z + a.w * b.w;
        }
#pragma unroll
        for (int off = 16; off > 0; off >>= 1) sum += __shfl_xor_sync(~0u, sum, off);
        if (lane == 0) g_v[k] = sum;
    } else if (k == IND) {
        float sum = 0.f;
#pragma unroll
        for (int i = 0; i < 4; i++) {
            float4 a = *(const float4*)(b_feat + lane * 4 + i * 128);
            float4 b = *(const float4*)(w_enc + lane * 4 + i * 128);
            sum += a.x * b.x + a.y * b.y + a.z * b.z + a.w * b.w;
        }
#pragma unroll
        for (int off = 16; off > 0; off >>= 1) sum += __shfl_xor_sync(~0u, sum, off);
        if (lane == 0) g_v[IND] = sum + b_enc[0];
    }
}

// ---------------- 0a) convert inputs -> bf16 hi/lo, warp-per-row, sync-free --
__global__ void __launch_bounds__(256) convert_inputs(const float* __restrict__ A)
{
    int warp = threadIdx.x >> 5, lane = threadIdx.x & 31;
    int row = blockIdx.x * 8 + warp;
    size_t rb = (size_t)row * IND;
    float dot = 0.f;
#pragma unroll
    for (int i = 0; i < 8; i++) {
        size_t o = rb + lane * 4 + i * 128;
        float4 v = *(const float4*)(A + o);
        __nv_bfloat16 h0 = __float2bfloat16(v.x), h1 = __float2bfloat16(v.y);
        __nv_bfloat16 h2 = __float2bfloat16(v.z), h3 = __float2bfloat16(v.w);
        __nv_bfloat16 l0 = __float2bfloat16(v.x - __bfloat162float(h0));
        __nv_bfloat16 l1 = __float2bfloat16(v.y - __bfloat162float(h1));
        __nv_bfloat16 l2 = __float2bfloat16(v.z - __bfloat162float(h2));
        __nv_bfloat16 l3 = __float2bfloat16(v.w - __bfloat162float(h3));
        *(ushort4*)(g_Ah + o) = make_ushort4(
            *(unsigned short*)&h0, *(unsigned short*)&h1,
            *(unsigned short*)&h2, *(unsigned short*)&h3);
        *(ushort4*)(g_Al + o) = make_ushort4(
            *(unsigned short*)&l0, *(unsigned short*)&l1,
            *(unsigned short*)&l2, *(unsigned short*)&l3);
        float4 w = *(const float4*)(g_v + lane * 4 + i * 128);
        dot += v.x * w.x + v.y * w.y + v.z * w.z + v.w * w.w;
    }
#pragma unroll
    for (int off = 16; off > 0; off >>= 1) dot += __shfl_xor_sync(~0u, dot, off);
    if (lane == 0) {
        float s = dot + g_v[IND];
        g_scores[row] = 1.f / (1.f + expf(-s));
    }
}

// ---------------- 1) HMMA bf16-split GEMM: x = A@W + b (round-12 proven) -----
#define GK_CH    32
#define TILE_B   8192
#define STAGE_B  (4*TILE_B)
#define NSTAGE   3
#define GEMM_SMEM (NSTAGE*STAGE_B)

__global__ void __launch_bounds__(256, 2) gemm_bf16(const float* __restrict__ bias)
{
    extern __shared__ __align__(1024) char sm[];
    const uint32_t smb = smem_u32(sm);
    const int tid = threadIdx.x;
    const int bx = blockIdx.x;
    const int by = blockIdx.y;

    const unsigned short* srcT[4] = {
        g_Ah  + (size_t)(by * 128) * IND,
        g_Al  + (size_t)(by * 128) * IND,
        g_Wth + (size_t)(bx * 128) * IND,
        g_Wtl + (size_t)(bx * 128) * IND };

    auto load_stage = [&](int stage, int chunk) {
        const int k0 = chunk * 32;
        uint32_t sbase = smb + stage * STAGE_B;
#pragma unroll
        for (int t = 0; t < 4; t++) {
            const unsigned short* src = srcT[t];
            uint32_t tb = sbase + t * TILE_B;
#pragma unroll
            for (int i = 0; i < 2; i++) {
                int q = i * 256 + tid;
                int row = q >> 2, c = q & 3;
                const unsigned short* gp = src + (size_t)row * IND + k0 + c * 8;
                uint32_t saddr = tb + row * 64 + ((c ^ ((row >> 1) & 3)) << 4);
                cp_async16(saddr, gp);
            }
        }
    };

    load_stage(0, 0); CP_COMMIT();
    load_stage(1, 1); CP_COMMIT();
    load_stage(2, 2); CP_COMMIT();

    const int wid = tid >> 5, lane = tid & 31;
    const int wm = wid >> 2;
    const int wn = wid & 3;
    const int rA = lane & 15;
    const int cAh = lane >> 4;
    const int sA = (rA >> 1) & 3;
    const uint32_t aRow = (uint32_t)(wm * 64 + rA) * 64;
    const int rB = (lane & 7) + ((lane >> 4) << 3);
    const int cBh = (lane >> 3) & 1;
    const int sB = (rB >> 1) & 3;
    const uint32_t bRow = (uint32_t)(wn * 32 + rB) * 64;

    float acc[16][4];
#pragma unroll
    for (int i = 0; i < 16; i++)
#pragma unroll
        for (int j = 0; j < 4; j++) acc[i][j] = 0.f;

    for (int chunk = 0; chunk < GK_CH; chunk++) {
        const int stage = chunk % NSTAGE;
        const uint32_t sbase = smb + stage * STAGE_B;
        CP_WAIT2();
        __syncthreads();

        uint32_t a[4][4], bb[2][4];
#pragma unroll
        for (int kk8 = 0; kk8 < 4; kk8 += 2) {
            const uint32_t aoff = (uint32_t)(((kk8 + cAh) ^ sA) << 4);
            const uint32_t boff = (uint32_t)(((kk8 + cBh) ^ sB) << 4);
#pragma unroll
            for (int im = 0; im < 4; im++)
                ldsm_x4(sbase + 0 * TILE_B + aRow + im * 1024 + aoff, a[im]);
#pragma unroll
            for (int i16 = 0; i16 < 2; i16++)
                ldsm_x4(sbase + 2 * TILE_B + bRow + i16 * 1024 + boff, bb[i16]);
#pragma unroll
            for (int im = 0; im < 4; im++)
#pragma unroll
                for (int n8 = 0; n8 < 4; n8++)
                    mma16816(acc[im * 4 + n8], a[im], &bb[n8 >> 1][(n8 & 1) * 2]);
#pragma unroll
            for (int i16 = 0; i16 < 2; i16++)
                ldsm_x4(sbase + 3 * TILE_B + bRow + i16 * 1024 + boff, bb[i16]);
#pragma unroll
            for (int im = 0; im < 4; im++)
#pragma unroll
                for (int n8 = 0; n8 < 4; n8++)
                    mma16816(acc[im * 4 + n8], a[im], &bb[n8 >> 1][(n8 & 1) * 2]);
#pragma unroll
            for (int im = 0; im < 4; im++)
                ldsm_x4(sbase + 1 * TILE_B + aRow + im * 1024 + aoff, a[im]);
#pragma unroll
            for (int i16 = 0; i16 < 2; i16++)
                ldsm_x4(sbase + 2 * TILE_B + bRow + i16 * 1024 + boff, bb[i16]);
#pragma unroll
            for (int im = 0; im < 4; im++)
#pragma unroll
                for (int n8 = 0; n8 < 4; n8++)
                    mma16816(acc[im * 4 + n8], a[im], &bb[n8 >> 1][(n8 & 1) * 2]);
        }
        __syncthreads();
        if (chunk + NSTAGE < GK_CH)
            load_stage((chunk + NSTAGE) % NSTAGE, chunk + NSTAGE);
        CP_COMMIT();
    }

    const int row0 = by * 128 + wm * 64 + (lane >> 2);
    const int colBase = bx * 128 + wn * 32 + (lane & 3) * 2;
#pragma unroll
    for (int im = 0; im < 4; im++) {
#pragma unroll
        for (int n8 = 0; n8 < 4; n8++) {
            int col = colBase + n8 * 8;
            float b0 = bias[col], b1 = bias[col + 1];
            float* d0 = g_x + (size_t)(row0 + im * 16) * HID + col;
            float* d1 = g_x + (size_t)(row0 + im * 16 + 8) * HID + col;
            *(float2*)d0 = make_float2(acc[im * 4 + n8][0] + b0, acc[im * 4 + n8][1] + b1);
            *(float2*)d1 = make_float2(acc[im * 4 + n8][2] + b0, acc[im * 4 + n8][3] + b1);
        }
    }
}

// ---------------- 3) sync-free two-stage top-16 + Q mean ---------------------
__global__ void __launch_bounds__(256) topk_kernel()
{
    __shared__ float cand_v[8 * KTOP];
    __shared__ int   cand_i[8 * KTOP];
    __shared__ int   idxs[KTOP];
    int b = blockIdx.x, tid = threadIdx.x;
    int warp = tid >> 5, lane = tid & 31;

    float v[32];
    const float* sp = g_scores + b * NN + warp * 1024;
#pragma unroll
    for (int i = 0; i < 32; i++) v[i] = sp[i * 32 + lane];

#pragma unroll 1
    for (int t = 0; t < KTOP; t++) {
        float m = -INFINITY; int mi = 0;
#pragma unroll
        for (int i = 0; i < 32; i++)
            if (v[i] > m) { m = v[i]; mi = i; }
        float bm = m; int bl = lane;
#pragma unroll
        for (int off = 16; off > 0; off >>= 1) {
            float om = __shfl_xor_sync(~0u, bm, off);
            int   ol = __shfl_xor_sync(~0u, bl, off);
            if (om > bm || (om == bm && ol < bl)) { bm = om; bl = ol; }
        }
        if (lane == bl) {
            cand_v[warp * KTOP + t] = m;
            cand_i[warp * KTOP + t] = warp * 1024 + mi * 32 + lane;
            v[mi] = -INFINITY;
        }
    }
    __syncthreads();

    if (warp == 0) {
        float cv[4]; int ci[4];
#pragma unroll
        for (int i = 0; i < 4; i++) {
            cv[i] = cand_v[i * 32 + lane];
            ci[i] = cand_i[i * 32 + lane];
        }
#pragma unroll 1
        for (int t = 0; t < KTOP; t++) {
            float m = -INFINITY; int mi = 0;
#pragma unroll
            for (int i = 0; i < 4; i++)
                if (cv[i] > m) { m = cv[i]; mi = i; }
            float bm = m; int bl = lane;
#pragma unroll
            for (int off = 16; off > 0; off >>= 1) {
                float om = __shfl_xor_sync(~0u, bm, off);
                int   ol = __shfl_xor_sync(~0u, bl, off);
                if (om > bm || (om == bm && ol < bl)) { bm = om; bl = ol; }
            }
            if (lane == bl) { idxs[t] = ci[mi]; cv[mi] = -INFINITY; }
        }
    }
    __syncthreads();

    for (int c = tid; c < HID; c += 256) {
        float sum = 0.f;
#pragma unroll
        for (int j = 0; j < KTOP; j++)
            sum += g_x[((size_t)b * NN + idxs[j]) * HID + c];
        g_Q[b * HID + c] = sum * (1.f / KTOP);
    }
}

// ---------------- 4) smem-tiled depthwise conv 3x3 + bias + residual ---------
__global__ void __launch_bounds__(256) conv_kernel(const float* __restrict__ conv_w,
                                                   const float* __restrict__ conv_b)
{
    __shared__ float st[100 * 64];
    int tid = threadIdx.x;
    int tile = blockIdx.x;
    int cg = blockIdx.y;
    int b = blockIdx.z;
    int ty = tile / 12, tx = tile % 12;
    int cgrp = tid & 15;
    int c0 = cg * 64 + cgrp * 4;

    float4 Qv = *(const float4*)&g_Q[b * HID + c0];

#pragma unroll
    for (int pass = 0; pass < 7; pass++) {
        int p = pass * 16 + (tid >> 4);
        if (p < 100) {
            int py = p / 10, px = p % 10;
            int hh = ty * 8 + py - 1, ww = tx * 8 + px - 1;
            float4 r = make_float4(0.f, 0.f, 0.f, 0.f);
            if ((unsigned)hh < HG && (unsigned)ww < HG) {
                int ss = hh * HG + ww;
                int smr = ss - (ss >= NN ? NN : 0);
                float4 v = *(const float4*)&g_x[((size_t)b * NN + smr) * HID + c0];
                r.x = fmaxf(v.x - Qv.x, 0.f);
                r.y = fmaxf(v.y - Qv.y, 0.f);
                r.z = fmaxf(v.z - Qv.z, 0.f);
                r.w = fmaxf(v.w - Qv.w, 0.f);
            }
            *(float4*)&st[p * 64 + cgrp * 4] = r;
        }
    }
    __syncthreads();

    float4 wt[9];
#pragma unroll
    for (int t = 0; t < 9; t++)
        wt[t] = make_float4(conv_w[(c0 + 0) * 9 + t], conv_w[(c0 + 1) * 9 + t],
                            conv_w[(c0 + 2) * 9 + t], conv_w[(c0 + 3) * 9 + t]);
    float4 bias4 = *(const float4*)(conv_b + c0);

#pragma unroll
    for (int i = 0; i < 4; i++) {
        int sp = i * 16 + (tid >> 4);
        int oy = sp >> 3, ox = sp & 7;
        int h = ty * 8 + oy, w = tx * 8 + ox;
        if (h < HG && w < HG) {
            float4 acc = bias4;
#pragma unroll
            for (int dy = 0; dy < 3; dy++) {
#pragma unroll
                for (int dx = 0; dx < 3; dx++) {
                    int pt = (oy + dy) * 10 + (ox + dx);
                    float4 v = *(const float4*)&st[pt * 64 + cgrp * 4];
                    float4 wv = wt[dy * 3 + dx];
                    acc.x += wv.x * v.x; acc.y += wv.y * v.y;
                    acc.z += wv.z * v.z; acc.w += wv.w * v.w;
                }
            }
            float4 ctr = *(const float4*)&st[((oy + 1) * 10 + (ox + 1)) * 64 + cgrp * 4];
            acc.x += ctr.x; acc.y += ctr.y; acc.z += ctr.z; acc.w += ctr.w;
            int s = h * HG + w;
            *(float4*)&g_y[((size_t)b * NP + s) * HID + c0] = acc;
        }
    }
}

// ---------------- 5a) prep1: q slice = Q@Wq+bq ; zero ctx/sume ; init out ----
// grid (BB, 8), block 64. Coalesced Wq access across 64 threads.
__global__ void __launch_bounds__(64) prep1_kernel(const float* __restrict__ Wq,
                                                   const float* __restrict__ bq,
                                                   const float* __restrict__ bc,
                                                   float* __restrict__ out)
{
    __shared__ float Qs[HID];
    int b = blockIdx.x, seg = blockIdx.y, tid = threadIdx.x;
    int hd = seg * 64 + tid;
#pragma unroll
    for (int i = 0; i < 8; i++) Qs[tid + i * 64] = g_Q[b * HID + tid + i * 64];
    __syncthreads();
    float sum = bq[hd];
    for (int c = 0; c < HID; c++) sum += Qs[c] * Wq[c * HID + hd];
    g_q[b * HID + hd] = sum;
    // zero ctx slice (this block owns head-seg row of ctx)
#pragma unroll
    for (int i = 0; i < 8; i++)
        g_ctx[b * HEADS * HID + seg * HID + tid + i * 64] = 0.f;
    if (seg == 0 && tid < HEADS) g_sume[b * HEADS + tid] = 0.f;
    if (seg == 0 && tid < NCLSD) out[b * NCLSD + tid] = bc[tid];
}

// ---------------- 5b) prep2: qWk fold per (b, head) + qbk --------------------
// grid (BB, HEADS), block 256: out[c] = sum_d q[h*64+d] * Wk[c*512 + h*64+d]
__global__ void __launch_bounds__(256) prep2_kernel(const float* __restrict__ Wk,
                                                    const float* __restrict__ bk)
{
    __shared__ float qh[DH];
    int b = blockIdx.x, h = blockIdx.y, tid = threadIdx.x;
    if (tid < DH) qh[tid] = g_q[b * HID + h * DH + tid];
    __syncthreads();
#pragma unroll
    for (int cc = 0; cc < 2; cc++) {
        int c = cc * 256 + tid;
        const float* wk = Wk + (size_t)c * HID + h * DH;
        float sum = 0.f;
#pragma unroll
        for (int d = 0; d < DH; d += 4) {
            float4 w = *(const float4*)(wk + d);
            sum += qh[d] * w.x + qh[d + 1] * w.y + qh[d + 2] * w.z + qh[d + 3] * w.w;
        }
        g_qWk[b * HEADS * HID + h * HID + c] = sum;
    }
    if (tid == 0) {
        float sum = 0.f;
#pragma unroll
        for (int d = 0; d < DH; d++) sum += qh[d] * bk[h * DH + d];
        g_qbk[b * HEADS + h] = sum;
    }
}

// ---------------- 6) fused logits+exp+ctx: one pass over tokens --------------
__global__ void __launch_bounds__(256) attn_fused(const float* __restrict__ cls)
{
    const float SCALE = 0.04419417382415922f;  // 1/sqrt(512)
    __shared__ float sw[HEADS * HID];
    __shared__ float sb[HEADS];
    __shared__ float wts[HEADS][128];
    int b = blockIdx.y, chunk = blockIdx.x, tid = threadIdx.x;
    int base = chunk * 128;
    int jmax = min(128, NT - base);
    for (int i = tid; i < HEADS * HID; i += 256) sw[i] = g_qWk[b * HEADS * HID + i];
    if (tid < HEADS) sb[tid] = g_qbk[b * HEADS + tid];
    __syncthreads();
    int warp = tid >> 5, lane = tid & 31;

    for (int p = 0; p < 16; p++) {
        int j = p * 8 + warp;
        int t = base + j;
        if (t >= NT) break;
        const float* tok = (t == 0) ? cls : (g_y + ((size_t)b * NP + (t - 1)) * HID);
        float acc[HEADS];
#pragma unroll
        for (int h = 0; h < HEADS; h++) acc[h] = 0.f;
#pragma unroll
        for (int i = 0; i < 4; i++) {
            float4 v = *(const float4*)(tok + lane * 4 + i * 128);
#pragma unroll
            for (int h = 0; h < HEADS; h++) {
                float4 w = *(const float4*)(sw + h * HID + lane * 4 + i * 128);
                acc[h] += v.x * w.x + v.y * w.y + v.z * w.z + v.w * w.w;
            }
        }
#pragma unroll
        for (int off = 16; off > 0; off >>= 1)
#pragma unroll
            for (int h = 0; h < HEADS; h++)
                acc[h] += __shfl_xor_sync(0xffffffffu, acc[h], off);
        if (lane < HEADS)
            wts[lane][j] = expf((acc[lane] + sb[lane]) * SCALE);
    }
    __syncthreads();

    {
        float s = 0.f;
        for (int j = lane; j < jmax; j += 32) s += wts[warp][j];
#pragma unroll
        for (int off = 16; off > 0; off >>= 1) s += __shfl_xor_sync(~0u, s, off);
        if (lane == 0) atomicAdd(&g_sume[b * HEADS + warp], s);
    }

    float r[2 * HEADS];
#pragma unroll
    for (int i = 0; i < 2 * HEADS; i++) r[i] = 0.f;
    int c0 = tid, c1 = tid + 256;
    for (int j = 0; j < jmax; j++) {
        int t = base + j;
        const float* tok = (t == 0) ? cls : (g_y + ((size_t)b * NP + (t - 1)) * HID);
        float v0 = tok[c0], v1 = tok[c1];
#pragma unroll
        for (int h = 0; h < HEADS; h++) {
            float w = wts[h][j];
            r[h]         += w * v0;
            r[h + HEADS] += w * v1;
        }
    }
#pragma unroll
    for (int h = 0; h < HEADS; h++) {
        atomicAdd(&g_ctx[b * HEADS * HID + h * HID + c0], r[h]);
        atomicAdd(&g_ctx[b * HEADS * HID + h * HID + c1], r[h + HEADS]);
    }
}

// ---------------- 9a) final1: sO slice = q + bv + (ctx/sume)@Wv --------------
// grid (BB, 8), block 64. Block's hd-range has fixed head h == seg.
__global__ void __launch_bounds__(64) final1_kernel(const float* __restrict__ Wv,
                                                    const float* __restrict__ bv)
{
    __shared__ float cs[HID];
    __shared__ float s_inv;
    int b = blockIdx.x, seg = blockIdx.y, tid = threadIdx.x;
    int hd = seg * 64 + tid;
    if (tid == 0) s_inv = 1.f / g_sume[b * HEADS + seg];
    __syncthreads();
    float inv = s_inv;
#pragma unroll
    for (int i = 0; i < 8; i++)
        cs[tid + i * 64] = g_ctx[b * HEADS * HID + seg * HID + tid + i * 64] * inv;
    __syncthreads();
    float sum = bv[hd] + g_q[b * HID + hd];
    for (int c = 0; c < HID; c++) sum += cs[c] * Wv[c * HID + hd];
    g_sO[b * HID + hd] = sum;
}

// ---------------- 9b) final2: sO2 slice + classifier partials ----------------
// grid (BB, 8), block 64; atomicAdd partial dots into pre-initialized d_out.
__global__ void __launch_bounds__(64) final2_kernel(const float* __restrict__ Wo,
                                                    const float* __restrict__ bo,
                                                    const float* __restrict__ Wc,
                                                    float* __restrict__ out)
{
    __shared__ float sO[HID];
    __shared__ float red0[2], red1[2];
    int b = blockIdx.x, seg = blockIdx.y, tid = threadIdx.x;
    int hd = seg * 64 + tid;
#pragma unroll
    for (int i = 0; i < 8; i++) sO[tid + i * 64] = g_sO[b * HID + tid + i * 64];
    __syncthreads();
    float sum = bo[hd];
    for (int c = 0; c < HID; c++) sum += sO[c] * Wo[c * HID + hd];
    float sO2 = sO[hd] + fmaxf(sum, 0.f);
    float p0 = sO2 * Wc[hd * NCLSD + 0];
    float p1 = sO2 * Wc[hd * NCLSD + 1];
    int lane = tid & 31, warp = tid >> 5;
#pragma unroll
    for (int off = 16; off > 0; off >>= 1) {
        p0 += __shfl_xor_sync(~0u, p0, off);
        p1 += __shfl_xor_sync(~0u, p1, off);
    }
    if (lane == 0) { red0[warp] = p0; red1[warp] = p1; }
    __syncthreads();
    if (tid == 0) {
        atomicAdd(&out[b * NCLSD + 0], red0[0] + red0[1]);
        atomicAdd(&out[b * NCLSD + 1], red1[0] + red1[1]);
    }
}

// ---------------- launch -----------------------------------------------------
extern "C" void kernel_launch(void* const* d_in, const int* in_sizes, int n_in,
                              void* d_out, int out_size)
{
    const float* inputs = (const float*)d_in[0];
    const float* W_feat = (const float*)d_in[1];
    const float* b_feat = (const float*)d_in[2];
    const float* w_enc  = (const float*)d_in[3];
    const float* b_enc  = (const float*)d_in[4];
    const float* cls    = (const float*)d_in[5];
    const float* conv_w = (const float*)d_in[6];
    const float* conv_b = (const float*)d_in[7];
    const float* Wq     = (const float*)d_in[8];
    const float* bq     = (const float*)d_in[9];
    const float* Wk     = (const float*)d_in[10];
    const float* bk     = (const float*)d_in[11];
    const float* Wv     = (const float*)d_in[12];
    const float* bv     = (const float*)d_in[13];
    const float* Wo     = (const float*)d_in[14];
    const float* bo     = (const float*)d_in[15];
    const float* Wc     = (const float*)d_in[16];
    const float* bc     = (const float*)d_in[17];
    float* out = (float*)d_out;

    cudaFuncSetAttribute(gemm_bf16, cudaFuncAttributeMaxDynamicSharedMemorySize,
                         GEMM_SMEM);

    prep_weights<<<2177, 256>>>(W_feat, w_enc, b_feat, b_enc);
    convert_inputs<<<MROWS / 8, 256>>>(inputs);  // also writes g_scores
    gemm_bf16<<<dim3(4, 256), 256, GEMM_SMEM>>>(b_feat);
    topk_kernel<<<BB, 256>>>();
    conv_kernel<<<dim3(144, 8, BB), 256>>>(conv_w, conv_b);
    prep1_kernel<<<dim3(BB, 8), 64>>>(Wq, bq, bc, out);
    prep2_kernel<<<dim3(BB, HEADS), 256>>>(Wk, bk);
    attn_fused<<<dim3(65, BB), 256>>>(cls);
    final1_kernel<<<dim3(BB, 8), 64>>>(Wv, bv);
    final2_kernel<<<dim3(BB, 8), 64>>>(Wo, bo, Wc, out);
}

// round 17
// speedup vs baseline: 1.2833x; 1.2833x over previous
#include <cuda_runtime.h>
#include <cuda_bf16.h>
#include <cstdint>
#include <math.h>

#define BB    4
#define NN    8192
#define IND   1024
#define HID   512
#define HEADS 8
#define DH    64
#define KTOP  16
#define NCLSD 2
#define HG    91
#define NP    (HG*HG)    /* 8281 */
#define NT    (NP+1)     /* 8282 */
#define MROWS (BB*NN)    /* 32768 */

// ---------------- scratch (device globals; no allocation allowed) ------------
__device__ float g_x[(size_t)MROWS*HID];           // post-feature GEMM (67 MB)
__device__ unsigned short g_Ah[(size_t)MROWS*IND]; // inputs hi bf16 (64 MB)
__device__ unsigned short g_Al[(size_t)MROWS*IND]; // inputs lo bf16 (64 MB)
__device__ unsigned short g_Wth[(size_t)HID*IND];  // W^T hi bf16
__device__ unsigned short g_Wtl[(size_t)HID*IND];  // W^T lo bf16
__device__ __align__(16) float g_v[IND + 4];       // folded score vector + const
__device__ float g_scores[MROWS];
__device__ float g_Q[BB*HID];
__device__ float g_y[(size_t)BB*NP*HID];           // post-conv tokens (68 MB)
__device__ float g_q[BB*HID];
__device__ float g_qWk[BB*HEADS*HID];
__device__ float g_qbk[BB*HEADS];
__device__ float g_sume[BB*HEADS];
__device__ float g_ctx[BB*HEADS*HID];

// =================== PTX helpers (arch-portable: ldmatrix/mma/cp.async) ======
__device__ __forceinline__ uint32_t smem_u32(const void* p) {
    uint32_t a;
    asm("{ .reg .u64 t; cvta.to.shared.u64 t, %1; cvt.u32.u64 %0, t; }"
        : "=r"(a) : "l"(p));
    return a;
}
__device__ __forceinline__ void ldsm_x4(uint32_t addr, uint32_t* r) {
    asm volatile("ldmatrix.sync.aligned.m8n8.x4.shared.b16 {%0,%1,%2,%3}, [%4];"
                 : "=r"(r[0]), "=r"(r[1]), "=r"(r[2]), "=r"(r[3]) : "r"(addr));
}
__device__ __forceinline__ void mma16816(float* c, const uint32_t* a,
                                         const uint32_t* b) {
    asm volatile(
        "mma.sync.aligned.m16n8k16.row.col.f32.bf16.bf16.f32 "
        "{%0,%1,%2,%3}, {%4,%5,%6,%7}, {%8,%9}, {%0,%1,%2,%3};"
        : "+f"(c[0]), "+f"(c[1]), "+f"(c[2]), "+f"(c[3])
        : "r"(a[0]), "r"(a[1]), "r"(a[2]), "r"(a[3]), "r"(b[0]), "r"(b[1]));
}
__device__ __forceinline__ void cp_async16(uint32_t saddr, const void* gptr) {
    asm volatile("cp.async.cg.shared.global [%0], [%1], 16;"
                 :: "r"(saddr), "l"(gptr));
}
#define CP_COMMIT() asm volatile("cp.async.commit_group;" ::: "memory")
#define CP_WAIT2()  asm volatile("cp.async.wait_group 2;" ::: "memory")

// ---------------- 0c) fold score vector: v = W_feat @ w_enc ------------------
__global__ void __launch_bounds__(256) fold_kernel(const float* __restrict__ W,
                                                   const float* __restrict__ w_enc,
                                                   const float* __restrict__ b_feat,
                                                   const float* __restrict__ b_enc)
{
    int warp = threadIdx.x >> 5, lane = threadIdx.x & 31;
    int k = blockIdx.x * 8 + warp;
    if (k < IND) {
        const float* Wr = W + (size_t)k * HID;
        float sum = 0.f;
#pragma unroll
        for (int i = 0; i < 4; i++) {
            float4 a = *(const float4*)(Wr + lane * 4 + i * 128);
            float4 b = *(const float4*)(w_enc + lane * 4 + i * 128);
            sum += a.x * b.x + a.y * b.y + a.z * b.z + a.w * b.w;
        }
#pragma unroll
        for (int off = 16; off > 0; off >>= 1) sum += __shfl_xor_sync(~0u, sum, off);
        if (lane == 0) g_v[k] = sum;
    } else if (k == IND) {
        float sum = 0.f;
#pragma unroll
        for (int i = 0; i < 4; i++) {
            float4 a = *(const float4*)(b_feat + lane * 4 + i * 128);
            float4 b = *(const float4*)(w_enc + lane * 4 + i * 128);
            sum += a.x * b.x + a.y * b.y + a.z * b.z + a.w * b.w;
        }
#pragma unroll
        for (int off = 16; off > 0; off >>= 1) sum += __shfl_xor_sync(~0u, sum, off);
        if (lane == 0) g_v[IND] = sum + b_enc[0];
    }
}

// ---------------- 0a) convert inputs -> bf16 hi/lo, warp-per-row, sync-free --
__global__ void __launch_bounds__(256) convert_inputs(const float* __restrict__ A)
{
    int warp = threadIdx.x >> 5, lane = threadIdx.x & 31;
    int row = blockIdx.x * 8 + warp;
    size_t rb = (size_t)row * IND;
    float dot = 0.f;
#pragma unroll
    for (int i = 0; i < 8; i++) {
        size_t o = rb + lane * 4 + i * 128;
        float4 v = *(const float4*)(A + o);
        __nv_bfloat16 h0 = __float2bfloat16(v.x), h1 = __float2bfloat16(v.y);
        __nv_bfloat16 h2 = __float2bfloat16(v.z), h3 = __float2bfloat16(v.w);
        __nv_bfloat16 l0 = __float2bfloat16(v.x - __bfloat162float(h0));
        __nv_bfloat16 l1 = __float2bfloat16(v.y - __bfloat162float(h1));
        __nv_bfloat16 l2 = __float2bfloat16(v.z - __bfloat162float(h2));
        __nv_bfloat16 l3 = __float2bfloat16(v.w - __bfloat162float(h3));
        *(ushort4*)(g_Ah + o) = make_ushort4(
            *(unsigned short*)&h0, *(unsigned short*)&h1,
            *(unsigned short*)&h2, *(unsigned short*)&h3);
        *(ushort4*)(g_Al + o) = make_ushort4(
            *(unsigned short*)&l0, *(unsigned short*)&l1,
            *(unsigned short*)&l2, *(unsigned short*)&l3);
        float4 w = *(const float4*)(g_v + lane * 4 + i * 128);
        dot += v.x * w.x + v.y * w.y + v.z * w.z + v.w * w.w;
    }
#pragma unroll
    for (int off = 16; off > 0; off >>= 1) dot += __shfl_xor_sync(~0u, dot, off);
    if (lane == 0) {
        float s = dot + g_v[IND];
        g_scores[row] = 1.f / (1.f + expf(-s));
    }
}

// ---------------- 0b) W^T bf16 hi/lo ----------------------------------------
__global__ void __launch_bounds__(256) convert_W(const float* __restrict__ W)
{
    int idx = blockIdx.x * 256 + threadIdx.x;
    int n = idx >> 10, k = idx & 1023;
    float v = W[(size_t)k * HID + n];
    __nv_bfloat16 h = __float2bfloat16(v);
    __nv_bfloat16 l = __float2bfloat16(v - __bfloat162float(h));
    g_Wth[idx] = *(unsigned short*)&h;
    g_Wtl[idx] = *(unsigned short*)&l;
}

// ---------------- 1) HMMA bf16-split GEMM: x = A@W + b (round-12 proven) -----
#define GK_CH    32
#define TILE_B   8192
#define STAGE_B  (4*TILE_B)
#define NSTAGE   3
#define GEMM_SMEM (NSTAGE*STAGE_B)

__global__ void __launch_bounds__(256, 2) gemm_bf16(const float* __restrict__ bias)
{
    extern __shared__ __align__(1024) char sm[];
    const uint32_t smb = smem_u32(sm);
    const int tid = threadIdx.x;
    const int bx = blockIdx.x;
    const int by = blockIdx.y;

    const unsigned short* srcT[4] = {
        g_Ah  + (size_t)(by * 128) * IND,
        g_Al  + (size_t)(by * 128) * IND,
        g_Wth + (size_t)(bx * 128) * IND,
        g_Wtl + (size_t)(bx * 128) * IND };

    auto load_stage = [&](int stage, int chunk) {
        const int k0 = chunk * 32;
        uint32_t sbase = smb + stage * STAGE_B;
#pragma unroll
        for (int t = 0; t < 4; t++) {
            const unsigned short* src = srcT[t];
            uint32_t tb = sbase + t * TILE_B;
#pragma unroll
            for (int i = 0; i < 2; i++) {
                int q = i * 256 + tid;
                int row = q >> 2, c = q & 3;
                const unsigned short* gp = src + (size_t)row * IND + k0 + c * 8;
                uint32_t saddr = tb + row * 64 + ((c ^ ((row >> 1) & 3)) << 4);
                cp_async16(saddr, gp);
            }
        }
    };

    load_stage(0, 0); CP_COMMIT();
    load_stage(1, 1); CP_COMMIT();
    load_stage(2, 2); CP_COMMIT();

    const int wid = tid >> 5, lane = tid & 31;
    const int wm = wid >> 2;
    const int wn = wid & 3;
    const int rA = lane & 15;
    const int cAh = lane >> 4;
    const int sA = (rA >> 1) & 3;
    const uint32_t aRow = (uint32_t)(wm * 64 + rA) * 64;
    const int rB = (lane & 7) + ((lane >> 4) << 3);
    const int cBh = (lane >> 3) & 1;
    const int sB = (rB >> 1) & 3;
    const uint32_t bRow = (uint32_t)(wn * 32 + rB) * 64;

    float acc[16][4];
#pragma unroll
    for (int i = 0; i < 16; i++)
#pragma unroll
        for (int j = 0; j < 4; j++) acc[i][j] = 0.f;

    for (int chunk = 0; chunk < GK_CH; chunk++) {
        const int stage = chunk % NSTAGE;
        const uint32_t sbase = smb + stage * STAGE_B;
        CP_WAIT2();
        __syncthreads();

        uint32_t a[4][4], bb[2][4];
#pragma unroll
        for (int kk8 = 0; kk8 < 4; kk8 += 2) {
            const uint32_t aoff = (uint32_t)(((kk8 + cAh) ^ sA) << 4);
            const uint32_t boff = (uint32_t)(((kk8 + cBh) ^ sB) << 4);
#pragma unroll
            for (int im = 0; im < 4; im++)
                ldsm_x4(sbase + 0 * TILE_B + aRow + im * 1024 + aoff, a[im]);
#pragma unroll
            for (int i16 = 0; i16 < 2; i16++)
                ldsm_x4(sbase + 2 * TILE_B + bRow + i16 * 1024 + boff, bb[i16]);
#pragma unroll
            for (int im = 0; im < 4; im++)
#pragma unroll
                for (int n8 = 0; n8 < 4; n8++)
                    mma16816(acc[im * 4 + n8], a[im], &bb[n8 >> 1][(n8 & 1) * 2]);
#pragma unroll
            for (int i16 = 0; i16 < 2; i16++)
                ldsm_x4(sbase + 3 * TILE_B + bRow + i16 * 1024 + boff, bb[i16]);
#pragma unroll
            for (int im = 0; im < 4; im++)
#pragma unroll
                for (int n8 = 0; n8 < 4; n8++)
                    mma16816(acc[im * 4 + n8], a[im], &bb[n8 >> 1][(n8 & 1) * 2]);
#pragma unroll
            for (int im = 0; im < 4; im++)
                ldsm_x4(sbase + 1 * TILE_B + aRow + im * 1024 + aoff, a[im]);
#pragma unroll
            for (int i16 = 0; i16 < 2; i16++)
                ldsm_x4(sbase + 2 * TILE_B + bRow + i16 * 1024 + boff, bb[i16]);
#pragma unroll
            for (int im = 0; im < 4; im++)
#pragma unroll
                for (int n8 = 0; n8 < 4; n8++)
                    mma16816(acc[im * 4 + n8], a[im], &bb[n8 >> 1][(n8 & 1) * 2]);
        }
        __syncthreads();
        if (chunk + NSTAGE < GK_CH)
            load_stage((chunk + NSTAGE) % NSTAGE, chunk + NSTAGE);
        CP_COMMIT();
    }

    const int row0 = by * 128 + wm * 64 + (lane >> 2);
    const int colBase = bx * 128 + wn * 32 + (lane & 3) * 2;
#pragma unroll
    for (int im = 0; im < 4; im++) {
#pragma unroll
        for (int n8 = 0; n8 < 4; n8++) {
            int col = colBase + n8 * 8;
            float b0 = bias[col], b1 = bias[col + 1];
            float* d0 = g_x + (size_t)(row0 + im * 16) * HID + col;
            float* d1 = g_x + (size_t)(row0 + im * 16 + 8) * HID + col;
            *(float2*)d0 = make_float2(acc[im * 4 + n8][0] + b0, acc[im * 4 + n8][1] + b1);
            *(float2*)d1 = make_float2(acc[im * 4 + n8][2] + b0, acc[im * 4 + n8][3] + b1);
        }
    }
}

// ---------------- 3) sync-free two-stage top-16 + Q mean ---------------------
__global__ void __launch_bounds__(256) topk_kernel()
{
    __shared__ float cand_v[8 * KTOP];
    __shared__ int   cand_i[8 * KTOP];
    __shared__ int   idxs[KTOP];
    int b = blockIdx.x, tid = threadIdx.x;
    int warp = tid >> 5, lane = tid & 31;

    float v[32];
    const float* sp = g_scores + b * NN + warp * 1024;
#pragma unroll
    for (int i = 0; i < 32; i++) v[i] = sp[i * 32 + lane];

#pragma unroll 1
    for (int t = 0; t < KTOP; t++) {
        float m = -INFINITY; int mi = 0;
#pragma unroll
        for (int i = 0; i < 32; i++)
            if (v[i] > m) { m = v[i]; mi = i; }
        float bm = m; int bl = lane;
#pragma unroll
        for (int off = 16; off > 0; off >>= 1) {
            float om = __shfl_xor_sync(~0u, bm, off);
            int   ol = __shfl_xor_sync(~0u, bl, off);
            if (om > bm || (om == bm && ol < bl)) { bm = om; bl = ol; }
        }
        if (lane == bl) {
            cand_v[warp * KTOP + t] = m;
            cand_i[warp * KTOP + t] = warp * 1024 + mi * 32 + lane;
            v[mi] = -INFINITY;
        }
    }
    __syncthreads();

    if (warp == 0) {
        float cv[4]; int ci[4];
#pragma unroll
        for (int i = 0; i < 4; i++) {
            cv[i] = cand_v[i * 32 + lane];
            ci[i] = cand_i[i * 32 + lane];
        }
#pragma unroll 1
        for (int t = 0; t < KTOP; t++) {
            float m = -INFINITY; int mi = 0;
#pragma unroll
            for (int i = 0; i < 4; i++)
                if (cv[i] > m) { m = cv[i]; mi = i; }
            float bm = m; int bl = lane;
#pragma unroll
            for (int off = 16; off > 0; off >>= 1) {
                float om = __shfl_xor_sync(~0u, bm, off);
                int   ol = __shfl_xor_sync(~0u, bl, off);
                if (om > bm || (om == bm && ol < bl)) { bm = om; bl = ol; }
            }
            if (lane == bl) { idxs[t] = ci[mi]; cv[mi] = -INFINITY; }
        }
    }
    __syncthreads();

    for (int c = tid; c < HID; c += 256) {
        float sum = 0.f;
#pragma unroll
        for (int j = 0; j < KTOP; j++)
            sum += g_x[((size_t)b * NN + idxs[j]) * HID + c];
        g_Q[b * HID + c] = sum * (1.f / KTOP);
    }
}

// ---------------- 4) smem-tiled depthwise conv 3x3 + bias + residual ---------
__global__ void __launch_bounds__(256) conv_kernel(const float* __restrict__ conv_w,
                                                   const float* __restrict__ conv_b)
{
    __shared__ float st[100 * 64];
    int tid = threadIdx.x;
    int tile = blockIdx.x;
    int cg = blockIdx.y;
    int b = blockIdx.z;
    int ty = tile / 12, tx = tile % 12;
    int cgrp = tid & 15;
    int c0 = cg * 64 + cgrp * 4;

    float4 Qv = *(const float4*)&g_Q[b * HID + c0];

#pragma unroll
    for (int pass = 0; pass < 7; pass++) {
        int p = pass * 16 + (tid >> 4);
        if (p < 100) {
            int py = p / 10, px = p % 10;
            int hh = ty * 8 + py - 1, ww = tx * 8 + px - 1;
            float4 r = make_float4(0.f, 0.f, 0.f, 0.f);
            if ((unsigned)hh < HG && (unsigned)ww < HG) {
                int ss = hh * HG + ww;
                int smr = ss - (ss >= NN ? NN : 0);
                float4 v = *(const float4*)&g_x[((size_t)b * NN + smr) * HID + c0];
                r.x = fmaxf(v.x - Qv.x, 0.f);
                r.y = fmaxf(v.y - Qv.y, 0.f);
                r.z = fmaxf(v.z - Qv.z, 0.f);
                r.w = fmaxf(v.w - Qv.w, 0.f);
            }
            *(float4*)&st[p * 64 + cgrp * 4] = r;
        }
    }
    __syncthreads();

    float4 wt[9];
#pragma unroll
    for (int t = 0; t < 9; t++)
        wt[t] = make_float4(conv_w[(c0 + 0) * 9 + t], conv_w[(c0 + 1) * 9 + t],
                            conv_w[(c0 + 2) * 9 + t], conv_w[(c0 + 3) * 9 + t]);
    float4 bias4 = *(const float4*)(conv_b + c0);

#pragma unroll
    for (int i = 0; i < 4; i++) {
        int sp = i * 16 + (tid >> 4);
        int oy = sp >> 3, ox = sp & 7;
        int h = ty * 8 + oy, w = tx * 8 + ox;
        if (h < HG && w < HG) {
            float4 acc = bias4;
#pragma unroll
            for (int dy = 0; dy < 3; dy++) {
#pragma unroll
                for (int dx = 0; dx < 3; dx++) {
                    int pt = (oy + dy) * 10 + (ox + dx);
                    float4 v = *(const float4*)&st[pt * 64 + cgrp * 4];
                    float4 wv = wt[dy * 3 + dx];
                    acc.x += wv.x * v.x; acc.y += wv.y * v.y;
                    acc.z += wv.z * v.z; acc.w += wv.w * v.w;
                }
            }
            float4 ctr = *(const float4*)&st[((oy + 1) * 10 + (ox + 1)) * 64 + cgrp * 4];
            acc.x += ctr.x; acc.y += ctr.y; acc.z += ctr.z; acc.w += ctr.w;
            int s = h * HG + w;
            *(float4*)&g_y[((size_t)b * NP + s) * HID + c0] = acc;
        }
    }
}

// ---------------- 5) q = Q@Wq+bq ; qWk fold ; qbk ; zero ctx+sume ------------
__global__ void __launch_bounds__(512) attn_prep_kernel(const float* __restrict__ Wq,
                                                        const float* __restrict__ bq,
                                                        const float* __restrict__ Wk,
                                                        const float* __restrict__ bk)
{
    __shared__ float Qs[HID];
    __shared__ float qs[HID];
    int b = blockIdx.x, tid = threadIdx.x;
    if (tid < HID) Qs[tid] = g_Q[b * HID + tid];
    __syncthreads();
    if (tid < HID) {
        float sum = bq[tid];
        for (int c = 0; c < HID; c++) sum += Qs[c] * Wq[c * HID + tid];
        qs[tid] = sum;
        g_q[b * HID + tid] = sum;
    }
    __syncthreads();
    for (int o = tid; o < HEADS * HID; o += 512) {
        int h = o >> 9, c = o & 511;
        const float* wk = Wk + c * HID + h * DH;
        const float* qq = qs + h * DH;
        float sum = 0.f;
#pragma unroll
        for (int d = 0; d < DH; d++) sum += qq[d] * wk[d];
        g_qWk[b * HEADS * HID + o] = sum;
    }
    if (tid < HEADS) {
        float sum = 0.f;
#pragma unroll
        for (int d = 0; d < DH; d++) sum += qs[tid * DH + d] * bk[tid * DH + d];
        g_qbk[b * HEADS + tid] = sum;
        g_sume[b * HEADS + tid] = 0.f;
    }
    for (int i = tid; i < HEADS * HID; i += 512) g_ctx[b * HEADS * HID + i] = 0.f;
}

// ---------------- 6) fused logits+exp+ctx: one pass over tokens --------------
__global__ void __launch_bounds__(256) attn_fused(const float* __restrict__ cls)
{
    const float SCALE = 0.04419417382415922f;  // 1/sqrt(512)
    __shared__ float sw[HEADS * HID];
    __shared__ float sb[HEADS];
    __shared__ float wts[HEADS][128];
    int b = blockIdx.y, chunk = blockIdx.x, tid = threadIdx.x;
    int base = chunk * 128;
    int jmax = min(128, NT - base);
    for (int i = tid; i < HEADS * HID; i += 256) sw[i] = g_qWk[b * HEADS * HID + i];
    if (tid < HEADS) sb[tid] = g_qbk[b * HEADS + tid];
    __syncthreads();
    int warp = tid >> 5, lane = tid & 31;

    for (int p = 0; p < 16; p++) {
        int j = p * 8 + warp;
        int t = base + j;
        if (t >= NT) break;
        const float* tok = (t == 0) ? cls : (g_y + ((size_t)b * NP + (t - 1)) * HID);
        float acc[HEADS];
#pragma unroll
        for (int h = 0; h < HEADS; h++) acc[h] = 0.f;
#pragma unroll
        for (int i = 0; i < 4; i++) {
            float4 v = *(const float4*)(tok + lane * 4 + i * 128);
#pragma unroll
            for (int h = 0; h < HEADS; h++) {
                float4 w = *(const float4*)(sw + h * HID + lane * 4 + i * 128);
                acc[h] += v.x * w.x + v.y * w.y + v.z * w.z + v.w * w.w;
            }
        }
#pragma unroll
        for (int off = 16; off > 0; off >>= 1)
#pragma unroll
            for (int h = 0; h < HEADS; h++)
                acc[h] += __shfl_xor_sync(0xffffffffu, acc[h], off);
        if (lane < HEADS)
            wts[lane][j] = expf((acc[lane] + sb[lane]) * SCALE);
    }
    __syncthreads();

    {
        float s = 0.f;
        for (int j = lane; j < jmax; j += 32) s += wts[warp][j];
#pragma unroll
        for (int off = 16; off > 0; off >>= 1) s += __shfl_xor_sync(~0u, s, off);
        if (lane == 0) atomicAdd(&g_sume[b * HEADS + warp], s);
    }

    float r[2 * HEADS];
#pragma unroll
    for (int i = 0; i < 2 * HEADS; i++) r[i] = 0.f;
    int c0 = tid, c1 = tid + 256;
    for (int j = 0; j < jmax; j++) {
        int t = base + j;
        const float* tok = (t == 0) ? cls : (g_y + ((size_t)b * NP + (t - 1)) * HID);
        float v0 = tok[c0], v1 = tok[c1];
#pragma unroll
        for (int h = 0; h < HEADS; h++) {
            float w = wts[h][j];
            r[h]         += w * v0;
            r[h + HEADS] += w * v1;
        }
    }
#pragma unroll
    for (int h = 0; h < HEADS; h++) {
        atomicAdd(&g_ctx[b * HEADS * HID + h * HID + c0], r[h]);
        atomicAdd(&g_ctx[b * HEADS * HID + h * HID + c1], r[h + HEADS]);
    }
}

// ---------------- 9) O (normalize ctx), Wo MLP, classifier -------------------
__global__ void __launch_bounds__(256) final_kernel(const float* __restrict__ Wv,
                                                    const float* __restrict__ bv,
                                                    const float* __restrict__ Wo,
                                                    const float* __restrict__ bo,
                                                    const float* __restrict__ Wc,
                                                    const float* __restrict__ bc,
                                                    float* __restrict__ out)
{
    __shared__ float sc[HEADS * HID];
    __shared__ float sO[HID];
    __shared__ float sO2[HID];
    __shared__ float inv[HEADS];
    __shared__ float red0[256], red1[256];
    int b = blockIdx.x, tid = threadIdx.x;
    if (tid < HEADS) inv[tid] = 1.f / g_sume[b * HEADS + tid];
    __syncthreads();
    for (int i = tid; i < HEADS * HID; i += 256)
        sc[i] = g_ctx[b * HEADS * HID + i] * inv[i >> 9];
    __syncthreads();
    for (int hd = tid; hd < HID; hd += 256) {
        int h = hd >> 6;
        float sum = bv[hd] + g_q[b * HID + hd];
        const float* cx = sc + h * HID;
        for (int c = 0; c < HID; c++) sum += cx[c] * Wv[c * HID + hd];
        sO[hd] = sum;
    }
    __syncthreads();
    for (int hd = tid; hd < HID; hd += 256) {
        float sum = bo[hd];
        for (int c = 0; c < HID; c++) sum += sO[c] * Wo[c * HID + hd];
        sO2[hd] = sO[hd] + fmaxf(sum, 0.f);
    }
    __syncthreads();
    float p0 = 0.f, p1 = 0.f;
    for (int c = tid; c < HID; c += 256) {
        p0 += sO2[c] * Wc[c * NCLSD + 0];
        p1 += sO2[c] * Wc[c * NCLSD + 1];
    }
    red0[tid] = p0; red1[tid] = p1;
    __syncthreads();
    for (int off = 128; off > 0; off >>= 1) {
        if (tid < off) { red0[tid] += red0[tid + off]; red1[tid] += red1[tid + off]; }
        __syncthreads();
    }
    if (tid == 0) {
        out[b * NCLSD + 0] = red0[0] + bc[0];
        out[b * NCLSD + 1] = red1[0] + bc[1];
    }
}

// ---------------- launch -----------------------------------------------------
extern "C" void kernel_launch(void* const* d_in, const int* in_sizes, int n_in,
                              void* d_out, int out_size)
{
    const float* inputs = (const float*)d_in[0];
    const float* W_feat = (const float*)d_in[1];
    const float* b_feat = (const float*)d_in[2];
    const float* w_enc  = (const float*)d_in[3];
    const float* b_enc  = (const float*)d_in[4];
    const float* cls    = (const float*)d_in[5];
    const float* conv_w = (const float*)d_in[6];
    const float* conv_b = (const float*)d_in[7];
    const float* Wq     = (const float*)d_in[8];
    const float* bq     = (const float*)d_in[9];
    const float* Wk     = (const float*)d_in[10];
    const float* bk     = (const float*)d_in[11];
    const float* Wv     = (const float*)d_in[12];
    const float* bv     = (const float*)d_in[13];
    const float* Wo     = (const float*)d_in[14];
    const float* bo     = (const float*)d_in[15];
    const float* Wc     = (const float*)d_in[16];
    const float* bc     = (const float*)d_in[17];
    float* out = (float*)d_out;

    cudaFuncSetAttribute(gemm_bf16, cudaFuncAttributeMaxDynamicSharedMemorySize,
                         GEMM_SMEM);

    fold_kernel<<<129, 256>>>(W_feat, w_enc, b_feat, b_enc);
    convert_inputs<<<MROWS / 8, 256>>>(inputs);  // also writes g_scores
    convert_W<<<(HID * IND) / 256, 256>>>(W_feat);
    gemm_bf16<<<dim3(4, 256), 256, GEMM_SMEM>>>(b_feat);
    topk_kernel<<<BB, 256>>>();
    conv_kernel<<<dim3(144, 8, BB), 256>>>(conv_w, conv_b);
    attn_prep_kernel<<<BB, 512>>>(Wq, bq, Wk, bk);
    attn_fused<<<dim3(65, BB), 256>>>(cls);
    final_kernel<<<BB, 256>>>(Wv, bv, Wo, bo, Wc, bc, out);
}